// round 3
// baseline (speedup 1.0000x reference)
#include <cuda_runtime.h>
#include <cstdint>

#define MAXV 50000
#define MAXE 800000
#define NODE_IN 128
#define EDGE_IN 16
#define HF 128
#define HEADS 4
#define OUTF 32
#define NEG_SLOPE 0.2f
#define ETILE 64

// ---------------- device scratch ----------------
__device__ float g_ft[MAXV * HF];
__device__ float g_el[MAXV * HEADS];
__device__ float g_er[MAXV * HEADS];
__device__ int   g_deg[MAXV];
__device__ int   g_incl[MAXV];
__device__ int   g_bsum[64];
__device__ int   g_rowptr[MAXV + 1];
__device__ int   g_cursor[MAXV];
__device__ int   g_csr[MAXE];
__device__ float g_wer[EDGE_IN * HEADS];

// ---------------- f32x2 helpers ----------------
__device__ __forceinline__ unsigned long long pack2(float x) {
    unsigned long long r;
    asm("mov.b64 %0, {%1, %1};" : "=l"(r) : "f"(x));
    return r;
}
__device__ __forceinline__ void fma2(unsigned long long& d, unsigned long long a, unsigned long long b) {
    asm("fma.rn.f32x2 %0, %1, %2, %0;" : "+l"(d) : "l"(a), "l"(b));
}
__device__ __forceinline__ float2 unpack2(unsigned long long v) {
    float2 f;
    asm("mov.b64 {%0, %1}, %2;" : "=f"(f.x), "=f"(f.y) : "l"(v));
    return f;
}

// ---------------- CSR-build kernels (side stream) ----------------
__global__ void k_zero(int V) {
    int i = blockIdx.x * blockDim.x + threadIdx.x;
    if (i < V) g_deg[i] = 0;
}

__global__ void k_hist(const int* __restrict__ dst, int E) {
    int i = blockIdx.x * blockDim.x + threadIdx.x;
    if (i < E) atomicAdd(&g_deg[dst[i]], 1);
}

__global__ void k_scan1(int V) {
    __shared__ int wsum[32];
    int b = blockIdx.x, t = threadIdx.x;
    int i = b * 1024 + t;
    int val = (i < V) ? g_deg[i] : 0;
    int lane = t & 31, wid = t >> 5;
    int x = val;
    #pragma unroll
    for (int o = 1; o < 32; o <<= 1) {
        int y = __shfl_up_sync(0xFFFFFFFFu, x, o);
        if (lane >= o) x += y;
    }
    if (lane == 31) wsum[wid] = x;
    __syncthreads();
    if (wid == 0) {
        int s = wsum[lane];
        #pragma unroll
        for (int o = 1; o < 32; o <<= 1) {
            int y = __shfl_up_sync(0xFFFFFFFFu, s, o);
            if (lane >= o) s += y;
        }
        wsum[lane] = s;
    }
    __syncthreads();
    int incl = x + (wid > 0 ? wsum[wid - 1] : 0);
    if (i < V) g_incl[i] = incl;
    if (t == 1023) g_bsum[b] = incl;
}

__global__ void k_scan3(int V) {
    __shared__ int soff;
    int b = blockIdx.x, t = threadIdx.x;
    if (t < 32) {
        int s = 0;
        for (int j = t; j < b; j += 32) s += g_bsum[j];
        #pragma unroll
        for (int o = 16; o > 0; o >>= 1) s += __shfl_xor_sync(0xFFFFFFFFu, s, o);
        if (t == 0) soff = s;
    }
    __syncthreads();
    int i = b * 1024 + t;
    if (i < V) {
        int incl = g_incl[i] + soff;
        g_rowptr[i + 1] = incl;
        g_cursor[i] = incl - g_deg[i];
        if (i == 0) g_rowptr[0] = 0;
    }
}

__global__ void k_fill(const int* __restrict__ dst, int E) {
    int i = blockIdx.x * blockDim.x + threadIdx.x;
    if (i < E) {
        int pos = atomicAdd(&g_cursor[dst[i]], 1);
        g_csr[pos] = i;
    }
}

// ---------------- main-chain kernels ----------------
__global__ void k_fold(const float* __restrict__ We, const float* __restrict__ ae) {
    int t = threadIdx.x;
    if (t < EDGE_IN * HEADS) {
        int j = t >> 2, h = t & 3;
        float s = 0.0f;
        #pragma unroll
        for (int f = 0; f < OUTF; f++)
            s += We[j * HF + h * OUTF + f] * ae[h * OUTF + f];
        g_wer[j * HEADS + h] = s;
    }
}

// node projection: ft = X@Wn, out = X@Wr + bias, fused el/er reductions.
__global__ void __launch_bounds__(256) k_nodeproj(
    const float* __restrict__ nf, const float* __restrict__ Wn,
    const float* __restrict__ Wr, const float* __restrict__ bias,
    const float* __restrict__ al, const float* __restrict__ ar,
    float* __restrict__ out, int V)
{
    __shared__ float xs[64][NODE_IN];
    int v0 = blockIdx.x * 64;
    int tid = threadIdx.x;

    #pragma unroll
    for (int i = 0; i < 8; i++) {
        int idx = tid + i * 256;
        int r = idx >> 5;
        int c4 = idx & 31;
        int v = v0 + r;
        float4 val = make_float4(0.f, 0.f, 0.f, 0.f);
        if (v < V) val = *reinterpret_cast<const float4*>(nf + (size_t)v * NODE_IN + c4 * 4);
        *reinterpret_cast<float4*>(&xs[r][c4 * 4]) = val;
    }
    __syncthreads();

    int cg = tid & 31;
    int rg = tid >> 5;

    unsigned long long an[8][2], arr[8][2];
    #pragma unroll
    for (int i = 0; i < 8; i++) {
        an[i][0] = an[i][1] = 0ull;
        arr[i][0] = arr[i][1] = 0ull;
    }

    #pragma unroll 2
    for (int k4 = 0; k4 < NODE_IN / 4; k4++) {
        float4 xr[8];
        #pragma unroll
        for (int i = 0; i < 8; i++)
            xr[i] = *reinterpret_cast<const float4*>(&xs[rg * 8 + i][k4 * 4]);
        #pragma unroll
        for (int kk = 0; kk < 4; kk++) {
            int k = k4 * 4 + kk;
            ulonglong2 wn = *reinterpret_cast<const ulonglong2*>(Wn + (size_t)k * HF + cg * 4);
            ulonglong2 wr = *reinterpret_cast<const ulonglong2*>(Wr + (size_t)k * HF + cg * 4);
            #pragma unroll
            for (int i = 0; i < 8; i++) {
                float x = (kk == 0) ? xr[i].x : (kk == 1) ? xr[i].y : (kk == 2) ? xr[i].z : xr[i].w;
                unsigned long long xb = pack2(x);
                fma2(an[i][0], xb, wn.x);
                fma2(an[i][1], xb, wn.y);
                fma2(arr[i][0], xb, wr.x);
                fma2(arr[i][1], xb, wr.y);
            }
        }
    }

    float4 b4 = *reinterpret_cast<const float4*>(bias + cg * 4);
    int h = cg >> 3;
    const float4 alv = __ldg(reinterpret_cast<const float4*>(al + h * OUTF + (cg & 7) * 4));
    const float4 arv = __ldg(reinterpret_cast<const float4*>(ar + h * OUTF + (cg & 7) * 4));

    #pragma unroll
    for (int i = 0; i < 8; i++) {
        int v = v0 + rg * 8 + i;
        float2 n0 = unpack2(an[i][0]), n1 = unpack2(an[i][1]);
        float2 r0 = unpack2(arr[i][0]), r1 = unpack2(arr[i][1]);
        float4 fv = make_float4(n0.x, n0.y, n1.x, n1.y);
        float4 rv = make_float4(r0.x + b4.x, r0.y + b4.y, r1.x + b4.z, r1.y + b4.w);
        if (v < V) {
            *reinterpret_cast<float4*>(g_ft + (size_t)v * HF + cg * 4) = fv;
            *reinterpret_cast<float4*>(out + (size_t)v * HF + cg * 4) = rv;
        }
        float pl = fv.x * alv.x + fv.y * alv.y + fv.z * alv.z + fv.w * alv.w;
        float pr = fv.x * arv.x + fv.y * arv.y + fv.z * arv.z + fv.w * arv.w;
        pl += __shfl_xor_sync(0xFFFFFFFFu, pl, 1);
        pl += __shfl_xor_sync(0xFFFFFFFFu, pl, 2);
        pl += __shfl_xor_sync(0xFFFFFFFFu, pl, 4);
        pr += __shfl_xor_sync(0xFFFFFFFFu, pr, 1);
        pr += __shfl_xor_sync(0xFFFFFFFFu, pr, 2);
        pr += __shfl_xor_sync(0xFFFFFFFFu, pr, 4);
        if ((cg & 7) == 0 && v < V) {
            g_el[v * HEADS + h] = pl;
            g_er[v * HEADS + h] = pr;
        }
    }
}

// ---------------- fully fused aggregation ----------------
// One block per dst node. Computes edge logits, exp, unnormalized weighted
// accumulation and the softmax denominator locally, then normalizes.
// (Softmax is shift-invariant + distributive over the segment; logits are O(1)
// so no max-subtraction needed.)
__global__ void __launch_bounds__(128) k_agg(const int* __restrict__ src,
                                             const float* __restrict__ ef,
                                             float* __restrict__ out, int V)
{
    __shared__ int    s_src[ETILE];
    __shared__ float  s_w[HEADS][ETILE];
    __shared__ float  s_wer[EDGE_IN * HEADS];
    __shared__ float4 s_red[3][32];
    __shared__ float  s_s[3][32];

    int v = blockIdx.x;
    int t = threadIdx.x, w = t >> 5, lane = t & 31;
    int beg = g_rowptr[v], end = g_rowptr[v + 1];
    if (end <= beg) return;

    if (t < EDGE_IN * HEADS) s_wer[t] = g_wer[t];

    float4 er4 = *reinterpret_cast<const float4*>(&g_er[v * HEADS]);

    int h = lane >> 3;
    float4 acc = make_float4(0.f, 0.f, 0.f, 0.f);
    float sacc = 0.0f;

    int e = t >> 1;         // edge slot in tile 0..63
    int half = t & 1;       // which 8 of 16 edge features

    for (int pos = beg; pos < end; pos += ETILE) {
        int cnt = min(ETILE, end - pos);
        __syncthreads();    // protects previous tile + s_wer on first iter

        // --- tile fill: 2 threads per edge compute ee + logit + exp ---
        bool valid = (e < cnt);
        int eid = g_csr[pos + (valid ? e : 0)];
        int sv = src[eid];
        float4 a4 = __ldg(reinterpret_cast<const float4*>(ef + (size_t)eid * EDGE_IN + half * 8));
        float4 c4 = __ldg(reinterpret_cast<const float4*>(ef + (size_t)eid * EDGE_IN + half * 8 + 4));
        float p0 = 0.f, p1 = 0.f, p2 = 0.f, p3 = 0.f;
        const float* wp = &s_wer[half * 8 * HEADS];
        {
            float fv[8] = {a4.x, a4.y, a4.z, a4.w, c4.x, c4.y, c4.z, c4.w};
            #pragma unroll
            for (int j = 0; j < 8; j++) {
                float x = fv[j];
                p0 += x * wp[j * 4 + 0];
                p1 += x * wp[j * 4 + 1];
                p2 += x * wp[j * 4 + 2];
                p3 += x * wp[j * 4 + 3];
            }
        }
        p0 += __shfl_xor_sync(0xFFFFFFFFu, p0, 1);
        p1 += __shfl_xor_sync(0xFFFFFFFFu, p1, 1);
        p2 += __shfl_xor_sync(0xFFFFFFFFu, p2, 1);
        p3 += __shfl_xor_sync(0xFFFFFFFFu, p3, 1);
        if (valid && half == 0) {
            s_src[e] = sv;
            float4 el4 = *reinterpret_cast<const float4*>(&g_el[sv * HEADS]);
            float t0 = el4.x + er4.x + p0;
            float t1 = el4.y + er4.y + p1;
            float t2 = el4.z + er4.z + p2;
            float t3 = el4.w + er4.w + p3;
            t0 = (t0 >= 0.f) ? t0 : NEG_SLOPE * t0;
            t1 = (t1 >= 0.f) ? t1 : NEG_SLOPE * t1;
            t2 = (t2 >= 0.f) ? t2 : NEG_SLOPE * t2;
            t3 = (t3 >= 0.f) ? t3 : NEG_SLOPE * t3;
            s_w[0][e] = __expf(t0);
            s_w[1][e] = __expf(t1);
            s_w[2][e] = __expf(t2);
            s_w[3][e] = __expf(t3);
        }
        __syncthreads();

        // --- accumulate: warp-per-edge, full 512B ft row per warp ---
        #pragma unroll 2
        for (int j = w; j < cnt; j += 4) {
            int s2 = s_src[j];
            float a = s_w[h][j];
            float4 f = __ldg(reinterpret_cast<const float4*>(g_ft + (size_t)s2 * HF + lane * 4));
            acc.x += a * f.x; acc.y += a * f.y; acc.z += a * f.z; acc.w += a * f.w;
            sacc += a;
        }
    }

    if (w > 0) { s_red[w - 1][lane] = acc; s_s[w - 1][lane] = sacc; }
    __syncthreads();
    if (w == 0) {
        acc.x += s_red[0][lane].x + s_red[1][lane].x + s_red[2][lane].x;
        acc.y += s_red[0][lane].y + s_red[1][lane].y + s_red[2][lane].y;
        acc.z += s_red[0][lane].z + s_red[1][lane].z + s_red[2][lane].z;
        acc.w += s_red[0][lane].w + s_red[1][lane].w + s_red[2][lane].w;
        sacc  += s_s[0][lane] + s_s[1][lane] + s_s[2][lane];
        float inv = 1.0f / sacc;
        float4* op = reinterpret_cast<float4*>(out + (size_t)v * HF + lane * 4);
        float4 o = *op;
        o.x += acc.x * inv; o.y += acc.y * inv; o.z += acc.z * inv; o.w += acc.w * inv;
        *op = o;
    }
}

// ---------------- launch with forked capture streams ----------------
static cudaStream_t g_s2 = nullptr;
static cudaEvent_t g_evFork = nullptr, g_evJoin = nullptr;

extern "C" void kernel_launch(void* const* d_in, const int* in_sizes, int n_in,
                              void* d_out, int out_size)
{
    const float* nf   = (const float*)d_in[0];
    const float* ef   = (const float*)d_in[1];
    const int*   src  = (const int*)d_in[2];
    const int*   dst  = (const int*)d_in[3];
    const float* Wn   = (const float*)d_in[4];
    const float* We   = (const float*)d_in[5];
    const float* al   = (const float*)d_in[6];
    const float* ar   = (const float*)d_in[7];
    const float* ae   = (const float*)d_in[8];
    const float* Wr   = (const float*)d_in[9];
    const float* bias = (const float*)d_in[10];
    float* out = (float*)d_out;

    int V = in_sizes[0] / NODE_IN;
    int E = in_sizes[2];
    if (V > MAXV) V = MAXV;
    if (E > MAXE) E = MAXE;

    if (!g_s2) {
        cudaStreamCreateWithFlags(&g_s2, cudaStreamNonBlocking);
        cudaEventCreateWithFlags(&g_evFork, cudaEventDisableTiming);
        cudaEventCreateWithFlags(&g_evJoin, cudaEventDisableTiming);
    }

    int nch = (V + 1023) / 1024;

    // fork side stream for CSR build
    cudaEventRecord(g_evFork, 0);
    cudaStreamWaitEvent(g_s2, g_evFork, 0);

    // submission order chosen so the ncu -s5-c1 window lands on k_nodeproj
    k_fold<<<1, 64>>>(We, ae);                               // #1 (main)
    k_zero<<<(V + 255) / 256, 256, 0, g_s2>>>(V);            // #2 (side)
    k_hist<<<(E + 255) / 256, 256, 0, g_s2>>>(dst, E);       // #3 (side)
    k_nodeproj<<<(V + 63) / 64, 256>>>(nf, Wn, Wr, bias, al, ar, out, V);  // #4 (main)
    k_scan1<<<nch, 1024, 0, g_s2>>>(V);                      // #5 (side)
    k_scan3<<<nch, 1024, 0, g_s2>>>(V);                      // #6 (side)
    k_fill<<<(E + 255) / 256, 256, 0, g_s2>>>(dst, E);       // #7 (side)
    cudaEventRecord(g_evJoin, g_s2);

    cudaStreamWaitEvent(0, g_evJoin, 0);
    k_agg<<<V, 128>>>(src, ef, out, V);                      // #8 (main)
}

// round 4
// speedup vs baseline: 1.2580x; 1.2580x over previous
#include <cuda_runtime.h>
#include <cstdint>

#define MAXV 50000
#define MAXE 800000
#define NODE_IN 128
#define EDGE_IN 16
#define HF 128
#define HEADS 4
#define OUTF 32
#define NEG_SLOPE 0.2f
#define ETILE 64

// ---------------- device scratch ----------------
__device__ float g_ft[MAXV * HF];
__device__ float g_el[MAXV * HEADS];
__device__ float g_er[MAXV * HEADS];
__device__ float g_esum[MAXV * HEADS];
__device__ float g_ex[MAXE * HEADS];
__device__ int   g_deg[MAXV];
__device__ int   g_incl[MAXV];
__device__ int   g_bsum[64];
__device__ int   g_rowptr[MAXV + 1];
__device__ int   g_cursor[MAXV];
__device__ int   g_csr[MAXE];
__device__ float g_wer[EDGE_IN * HEADS];

// ---------------- f32x2 helpers ----------------
__device__ __forceinline__ unsigned long long pack2(float x) {
    unsigned long long r;
    asm("mov.b64 %0, {%1, %1};" : "=l"(r) : "f"(x));
    return r;
}
__device__ __forceinline__ void fma2(unsigned long long& d, unsigned long long a, unsigned long long b) {
    asm("fma.rn.f32x2 %0, %1, %2, %0;" : "+l"(d) : "l"(a), "l"(b));
}
__device__ __forceinline__ float2 unpack2(unsigned long long v) {
    float2 f;
    asm("mov.b64 {%0, %1}, %2;" : "=f"(f.x), "=f"(f.y) : "l"(v));
    return f;
}

// ---------------- CSR-build kernels (side stream) ----------------
__global__ void k_zero(int V) {
    int i = blockIdx.x * blockDim.x + threadIdx.x;
    if (i < V) g_deg[i] = 0;
    if (i < V * HEADS) g_esum[i] = 0.0f;
}

__global__ void k_hist(const int* __restrict__ dst, int E) {
    int i = blockIdx.x * blockDim.x + threadIdx.x;
    if (i < E) atomicAdd(&g_deg[dst[i]], 1);
}

__global__ void k_scan1(int V) {
    __shared__ int wsum[32];
    int b = blockIdx.x, t = threadIdx.x;
    int i = b * 1024 + t;
    int val = (i < V) ? g_deg[i] : 0;
    int lane = t & 31, wid = t >> 5;
    int x = val;
    #pragma unroll
    for (int o = 1; o < 32; o <<= 1) {
        int y = __shfl_up_sync(0xFFFFFFFFu, x, o);
        if (lane >= o) x += y;
    }
    if (lane == 31) wsum[wid] = x;
    __syncthreads();
    if (wid == 0) {
        int s = wsum[lane];
        #pragma unroll
        for (int o = 1; o < 32; o <<= 1) {
            int y = __shfl_up_sync(0xFFFFFFFFu, s, o);
            if (lane >= o) s += y;
        }
        wsum[lane] = s;
    }
    __syncthreads();
    int incl = x + (wid > 0 ? wsum[wid - 1] : 0);
    if (i < V) g_incl[i] = incl;
    if (t == 1023) g_bsum[b] = incl;
}

__global__ void k_scan3(int V) {
    __shared__ int soff;
    int b = blockIdx.x, t = threadIdx.x;
    if (t < 32) {
        int s = 0;
        for (int j = t; j < b; j += 32) s += g_bsum[j];
        #pragma unroll
        for (int o = 16; o > 0; o >>= 1) s += __shfl_xor_sync(0xFFFFFFFFu, s, o);
        if (t == 0) soff = s;
    }
    __syncthreads();
    int i = b * 1024 + t;
    if (i < V) {
        int incl = g_incl[i] + soff;
        g_rowptr[i + 1] = incl;
        g_cursor[i] = incl - g_deg[i];
        if (i == 0) g_rowptr[0] = 0;
    }
}

__global__ void k_fill(const int* __restrict__ dst, int E) {
    int i = blockIdx.x * blockDim.x + threadIdx.x;
    if (i < E) {
        int pos = atomicAdd(&g_cursor[dst[i]], 1);
        g_csr[pos] = i;
    }
}

// ---------------- main-chain kernels ----------------
__global__ void k_fold(const float* __restrict__ We, const float* __restrict__ ae) {
    int t = threadIdx.x;
    if (t < EDGE_IN * HEADS) {
        int j = t >> 2, h = t & 3;
        float s = 0.0f;
        #pragma unroll
        for (int f = 0; f < OUTF; f++)
            s += We[j * HF + h * OUTF + f] * ae[h * OUTF + f];
        g_wer[j * HEADS + h] = s;
    }
}

// node projection: ft = X@Wn, out = X@Wr + bias, fused el/er reductions.
// 512 threads, 64 rows per block: warp w -> rows w*4..w*4+3, lane -> 4 cols.
// Per-thread accumulators: 4 rows x 4 cols x 2 mats = 16 f32x2 = 32 regs ->
// target ~90 regs, 16 warps/SM (4 per SMSP) for latency hiding.
__global__ void __launch_bounds__(512) k_nodeproj(
    const float* __restrict__ nf, const float* __restrict__ Wn,
    const float* __restrict__ Wr, const float* __restrict__ bias,
    const float* __restrict__ al, const float* __restrict__ ar,
    float* __restrict__ out, int V)
{
    __shared__ float xs[64][NODE_IN];
    int v0 = blockIdx.x * 64;
    int tid = threadIdx.x;

    #pragma unroll
    for (int i = 0; i < 4; i++) {
        int idx = tid + i * 512;          // 0..2047
        int r = idx >> 5;                 // row 0..63
        int c4 = idx & 31;
        int v = v0 + r;
        float4 val = make_float4(0.f, 0.f, 0.f, 0.f);
        if (v < V) val = *reinterpret_cast<const float4*>(nf + (size_t)v * NODE_IN + c4 * 4);
        *reinterpret_cast<float4*>(&xs[r][c4 * 4]) = val;
    }
    __syncthreads();

    int cg = tid & 31;
    int w = tid >> 5;                     // warp 0..15 -> rows w*4..w*4+3

    unsigned long long an[4][2], arr[4][2];
    #pragma unroll
    for (int i = 0; i < 4; i++) {
        an[i][0] = an[i][1] = 0ull;
        arr[i][0] = arr[i][1] = 0ull;
    }

    #pragma unroll 4
    for (int k4 = 0; k4 < NODE_IN / 4; k4++) {
        float4 xr[4];
        #pragma unroll
        for (int i = 0; i < 4; i++)
            xr[i] = *reinterpret_cast<const float4*>(&xs[w * 4 + i][k4 * 4]);
        #pragma unroll
        for (int kk = 0; kk < 4; kk++) {
            int k = k4 * 4 + kk;
            ulonglong2 wn = *reinterpret_cast<const ulonglong2*>(Wn + (size_t)k * HF + cg * 4);
            ulonglong2 wr = *reinterpret_cast<const ulonglong2*>(Wr + (size_t)k * HF + cg * 4);
            #pragma unroll
            for (int i = 0; i < 4; i++) {
                float x = (kk == 0) ? xr[i].x : (kk == 1) ? xr[i].y : (kk == 2) ? xr[i].z : xr[i].w;
                unsigned long long xb = pack2(x);
                fma2(an[i][0], xb, wn.x);
                fma2(an[i][1], xb, wn.y);
                fma2(arr[i][0], xb, wr.x);
                fma2(arr[i][1], xb, wr.y);
            }
        }
    }

    float4 b4 = *reinterpret_cast<const float4*>(bias + cg * 4);
    int h = cg >> 3;
    const float4 alv = __ldg(reinterpret_cast<const float4*>(al + h * OUTF + (cg & 7) * 4));
    const float4 arv = __ldg(reinterpret_cast<const float4*>(ar + h * OUTF + (cg & 7) * 4));

    #pragma unroll
    for (int i = 0; i < 4; i++) {
        int v = v0 + w * 4 + i;
        float2 n0 = unpack2(an[i][0]), n1 = unpack2(an[i][1]);
        float2 r0 = unpack2(arr[i][0]), r1 = unpack2(arr[i][1]);
        float4 fv = make_float4(n0.x, n0.y, n1.x, n1.y);
        float4 rv = make_float4(r0.x + b4.x, r0.y + b4.y, r1.x + b4.z, r1.y + b4.w);
        if (v < V) {
            *reinterpret_cast<float4*>(g_ft + (size_t)v * HF + cg * 4) = fv;
            *reinterpret_cast<float4*>(out + (size_t)v * HF + cg * 4) = rv;
        }
        float pl = fv.x * alv.x + fv.y * alv.y + fv.z * alv.z + fv.w * alv.w;
        float pr = fv.x * arv.x + fv.y * arv.y + fv.z * arv.z + fv.w * arv.w;
        pl += __shfl_xor_sync(0xFFFFFFFFu, pl, 1);
        pl += __shfl_xor_sync(0xFFFFFFFFu, pl, 2);
        pl += __shfl_xor_sync(0xFFFFFFFFu, pl, 4);
        pr += __shfl_xor_sync(0xFFFFFFFFu, pr, 1);
        pr += __shfl_xor_sync(0xFFFFFFFFu, pr, 2);
        pr += __shfl_xor_sync(0xFFFFFFFFu, pr, 4);
        if ((cg & 7) == 0 && v < V) {
            g_el[v * HEADS + h] = pl;
            g_er[v * HEADS + h] = pr;
        }
    }
}

// edge logits + exp + segment-sum denominator (contiguous ef reads)
__global__ void k_edge(const float* __restrict__ ef, const int* __restrict__ src,
                       const int* __restrict__ dst, int E)
{
    __shared__ float swer[EDGE_IN * HEADS];
    if (threadIdx.x < EDGE_IN * HEADS) swer[threadIdx.x] = g_wer[threadIdx.x];
    __syncthreads();

    int i = blockIdx.x * blockDim.x + threadIdx.x;
    if (i >= E) return;

    float efv[16];
    #pragma unroll
    for (int q = 0; q < 4; q++) {
        float4 e4 = __ldg(reinterpret_cast<const float4*>(ef + (size_t)i * EDGE_IN + q * 4));
        efv[q * 4 + 0] = e4.x; efv[q * 4 + 1] = e4.y; efv[q * 4 + 2] = e4.z; efv[q * 4 + 3] = e4.w;
    }
    float ee0 = 0.f, ee1 = 0.f, ee2 = 0.f, ee3 = 0.f;
    #pragma unroll
    for (int j = 0; j < EDGE_IN; j++) {
        float e = efv[j];
        ee0 += e * swer[j * 4 + 0];
        ee1 += e * swer[j * 4 + 1];
        ee2 += e * swer[j * 4 + 2];
        ee3 += e * swer[j * 4 + 3];
    }

    int s = src[i], d = dst[i];
    float4 el4 = *reinterpret_cast<const float4*>(&g_el[s * HEADS]);
    float4 er4 = *reinterpret_cast<const float4*>(&g_er[d * HEADS]);

    float t0 = el4.x + er4.x + ee0;
    float t1 = el4.y + er4.y + ee1;
    float t2 = el4.z + er4.z + ee2;
    float t3 = el4.w + er4.w + ee3;
    t0 = (t0 >= 0.f) ? t0 : NEG_SLOPE * t0;
    t1 = (t1 >= 0.f) ? t1 : NEG_SLOPE * t1;
    t2 = (t2 >= 0.f) ? t2 : NEG_SLOPE * t2;
    t3 = (t3 >= 0.f) ? t3 : NEG_SLOPE * t3;
    // softmax is shift-invariant, logits are O(1): no max pass needed
    float x0 = __expf(t0), x1 = __expf(t1), x2 = __expf(t2), x3 = __expf(t3);

    *reinterpret_cast<float4*>(&g_ex[(size_t)i * HEADS]) = make_float4(x0, x1, x2, x3);

    float* ep = &g_esum[d * HEADS];
    asm volatile("red.global.add.v4.f32 [%0], {%1,%2,%3,%4};"
                 :: "l"(ep), "f"(x0), "f"(x1), "f"(x2), "f"(x3) : "memory");
}

// aggregation: one block per dst, warp-per-edge float4 gathers
__global__ void __launch_bounds__(128) k_agg(const int* __restrict__ src,
                                             float* __restrict__ out, int V)
{
    __shared__ int   s_src[ETILE];
    __shared__ float s_a[HEADS][ETILE];
    __shared__ float4 s_red[3][32];

    int v = blockIdx.x;
    int t = threadIdx.x, w = t >> 5, lane = t & 31;
    int beg = g_rowptr[v], end = g_rowptr[v + 1];
    if (end <= beg) return;

    float4 es = *reinterpret_cast<const float4*>(&g_esum[v * HEADS]);
    float iv0 = 1.0f / es.x, iv1 = 1.0f / es.y, iv2 = 1.0f / es.z, iv3 = 1.0f / es.w;

    int h = lane >> 3;
    float4 acc = make_float4(0.f, 0.f, 0.f, 0.f);

    for (int pos = beg; pos < end; pos += ETILE) {
        int cnt = min(ETILE, end - pos);
        __syncthreads();
        if (t < cnt) {
            int eid = g_csr[pos + t];
            s_src[t] = src[eid];
            float4 ex = *reinterpret_cast<const float4*>(&g_ex[(size_t)eid * HEADS]);
            s_a[0][t] = ex.x * iv0;
            s_a[1][t] = ex.y * iv1;
            s_a[2][t] = ex.z * iv2;
            s_a[3][t] = ex.w * iv3;
        }
        __syncthreads();
        #pragma unroll 2
        for (int j = w; j < cnt; j += 4) {
            int sv = s_src[j];
            float a = s_a[h][j];
            float4 f = __ldg(reinterpret_cast<const float4*>(g_ft + (size_t)sv * HF + lane * 4));
            acc.x += a * f.x; acc.y += a * f.y; acc.z += a * f.z; acc.w += a * f.w;
        }
    }

    if (w > 0) s_red[w - 1][lane] = acc;
    __syncthreads();
    if (w == 0) {
        acc.x += s_red[0][lane].x + s_red[1][lane].x + s_red[2][lane].x;
        acc.y += s_red[0][lane].y + s_red[1][lane].y + s_red[2][lane].y;
        acc.z += s_red[0][lane].z + s_red[1][lane].z + s_red[2][lane].z;
        acc.w += s_red[0][lane].w + s_red[1][lane].w + s_red[2][lane].w;
        float4* op = reinterpret_cast<float4*>(out + (size_t)v * HF + lane * 4);
        float4 o = *op;
        o.x += acc.x; o.y += acc.y; o.z += acc.z; o.w += acc.w;
        *op = o;
    }
}

// ---------------- launch with forked capture streams ----------------
static cudaStream_t g_s2 = nullptr;
static cudaEvent_t g_evFork = nullptr, g_evJoin = nullptr, g_evZ = nullptr;

extern "C" void kernel_launch(void* const* d_in, const int* in_sizes, int n_in,
                              void* d_out, int out_size)
{
    const float* nf   = (const float*)d_in[0];
    const float* ef   = (const float*)d_in[1];
    const int*   src  = (const int*)d_in[2];
    const int*   dst  = (const int*)d_in[3];
    const float* Wn   = (const float*)d_in[4];
    const float* We   = (const float*)d_in[5];
    const float* al   = (const float*)d_in[6];
    const float* ar   = (const float*)d_in[7];
    const float* ae   = (const float*)d_in[8];
    const float* Wr   = (const float*)d_in[9];
    const float* bias = (const float*)d_in[10];
    float* out = (float*)d_out;

    int V = in_sizes[0] / NODE_IN;
    int E = in_sizes[2];
    if (V > MAXV) V = MAXV;
    if (E > MAXE) E = MAXE;

    if (!g_s2) {
        cudaStreamCreateWithFlags(&g_s2, cudaStreamNonBlocking);
        cudaEventCreateWithFlags(&g_evFork, cudaEventDisableTiming);
        cudaEventCreateWithFlags(&g_evJoin, cudaEventDisableTiming);
        cudaEventCreateWithFlags(&g_evZ, cudaEventDisableTiming);
    }

    int nch = (V + 1023) / 1024;

    // fork side stream for CSR build + esum zeroing
    cudaEventRecord(g_evFork, 0);
    cudaStreamWaitEvent(g_s2, g_evFork, 0);

    k_fold<<<1, 64>>>(We, ae);                                     // #1 main
    k_zero<<<(V * HEADS + 255) / 256, 256, 0, g_s2>>>(V);          // #2 side
    cudaEventRecord(g_evZ, g_s2);
    k_hist<<<(E + 255) / 256, 256, 0, g_s2>>>(dst, E);             // #3 side
    k_nodeproj<<<(V + 63) / 64, 512>>>(nf, Wn, Wr, bias, al, ar, out, V);  // #4 main (profiled)
    k_scan1<<<nch, 1024, 0, g_s2>>>(V);                            // #5 side
    k_scan3<<<nch, 1024, 0, g_s2>>>(V);                            // #6 side
    k_fill<<<(E + 255) / 256, 256, 0, g_s2>>>(dst, E);             // #7 side
    cudaEventRecord(g_evJoin, g_s2);

    cudaStreamWaitEvent(0, g_evZ, 0);
    k_edge<<<(E + 127) / 128, 128>>>(ef, src, dst, E);             // #8 main

    cudaStreamWaitEvent(0, g_evJoin, 0);
    k_agg<<<V, 128>>>(src, out, V);                                // #9 main
}

// round 5
// speedup vs baseline: 1.6348x; 1.2995x over previous
#include <cuda_runtime.h>
#include <cstdint>

#define MAXV 50000
#define MAXE 800000
#define NODE_IN 128
#define EDGE_IN 16
#define HF 128
#define HEADS 4
#define OUTF 32
#define NEG_SLOPE 0.2f
#define ETILE 64
#define PROJ_ROWS 128

// ---------------- device scratch ----------------
__device__ float g_ft[MAXV * HF];
__device__ float g_el[MAXV * HEADS];
__device__ float g_er[MAXV * HEADS];
__device__ float g_esum[MAXV * HEADS];
__device__ float g_ex[MAXE * HEADS];
__device__ int   g_deg[MAXV];
__device__ int   g_incl[MAXV];
__device__ int   g_bsum[64];
__device__ int   g_rowptr[MAXV + 1];
__device__ int   g_cursor[MAXV];
__device__ int   g_csr[MAXE];
__device__ float g_wer[EDGE_IN * HEADS];

// ---------------- f32x2 helpers ----------------
__device__ __forceinline__ unsigned long long pack2(float x) {
    unsigned long long r;
    asm("mov.b64 %0, {%1, %1};" : "=l"(r) : "f"(x));
    return r;
}
__device__ __forceinline__ void fma2(unsigned long long& d, unsigned long long a, unsigned long long b) {
    asm("fma.rn.f32x2 %0, %1, %2, %0;" : "+l"(d) : "l"(a), "l"(b));
}
__device__ __forceinline__ float2 unpack2(unsigned long long v) {
    float2 f;
    asm("mov.b64 {%0, %1}, %2;" : "=f"(f.x), "=f"(f.y) : "l"(v));
    return f;
}

// ---------------- CSR-build kernels (side stream) ----------------
__global__ void k_zero(int V) {
    int i = blockIdx.x * blockDim.x + threadIdx.x;
    if (i < V) g_deg[i] = 0;
    if (i < V * HEADS) g_esum[i] = 0.0f;
}

__global__ void k_hist(const int* __restrict__ dst, int E) {
    int i = blockIdx.x * blockDim.x + threadIdx.x;
    if (i < E) atomicAdd(&g_deg[dst[i]], 1);
}

__global__ void k_scan1(int V) {
    __shared__ int wsum[32];
    int b = blockIdx.x, t = threadIdx.x;
    int i = b * 1024 + t;
    int val = (i < V) ? g_deg[i] : 0;
    int lane = t & 31, wid = t >> 5;
    int x = val;
    #pragma unroll
    for (int o = 1; o < 32; o <<= 1) {
        int y = __shfl_up_sync(0xFFFFFFFFu, x, o);
        if (lane >= o) x += y;
    }
    if (lane == 31) wsum[wid] = x;
    __syncthreads();
    if (wid == 0) {
        int s = wsum[lane];
        #pragma unroll
        for (int o = 1; o < 32; o <<= 1) {
            int y = __shfl_up_sync(0xFFFFFFFFu, s, o);
            if (lane >= o) s += y;
        }
        wsum[lane] = s;
    }
    __syncthreads();
    int incl = x + (wid > 0 ? wsum[wid - 1] : 0);
    if (i < V) g_incl[i] = incl;
    if (t == 1023) g_bsum[b] = incl;
}

__global__ void k_scan3(int V) {
    __shared__ int soff;
    int b = blockIdx.x, t = threadIdx.x;
    if (t < 32) {
        int s = 0;
        for (int j = t; j < b; j += 32) s += g_bsum[j];
        #pragma unroll
        for (int o = 16; o > 0; o >>= 1) s += __shfl_xor_sync(0xFFFFFFFFu, s, o);
        if (t == 0) soff = s;
    }
    __syncthreads();
    int i = b * 1024 + t;
    if (i < V) {
        int incl = g_incl[i] + soff;
        g_rowptr[i + 1] = incl;
        g_cursor[i] = incl - g_deg[i];
        if (i == 0) g_rowptr[0] = 0;
    }
}

__global__ void k_fill(const int* __restrict__ dst, int E) {
    int i = blockIdx.x * blockDim.x + threadIdx.x;
    if (i < E) {
        int pos = atomicAdd(&g_cursor[dst[i]], 1);
        g_csr[pos] = i;
    }
}

// ---------------- main-chain kernels ----------------
__global__ void k_fold(const float* __restrict__ We, const float* __restrict__ ae) {
    int t = threadIdx.x;
    if (t < EDGE_IN * HEADS) {
        int j = t >> 2, h = t & 3;
        float s = 0.0f;
        #pragma unroll
        for (int f = 0; f < OUTF; f++)
            s += We[j * HF + h * OUTF + f] * ae[h * OUTF + f];
        g_wer[j * HEADS + h] = s;
    }
}

// node projection: ft = X@Wn, out = X@Wr + bias, fused el/er.
// 512 threads, 128 rows/block, 8 rows/thread (warp w -> rows w*8..w*8+7).
// Weights hoisted per k4 and reused across the 8 rows -> fma:L1wf = 2:1.
// xs reads are warp-broadcasts (free).
__global__ void __launch_bounds__(512) k_nodeproj(
    const float* __restrict__ nf, const float* __restrict__ Wn,
    const float* __restrict__ Wr, const float* __restrict__ bias,
    const float* __restrict__ al, const float* __restrict__ ar,
    float* __restrict__ out, int V)
{
    extern __shared__ float xs[];   // [PROJ_ROWS][NODE_IN] = 64 KB
    int v0 = blockIdx.x * PROJ_ROWS;
    int tid = threadIdx.x;

    #pragma unroll
    for (int i = 0; i < 8; i++) {
        int idx = tid + i * 512;          // 0..4095
        int r = idx >> 5;                 // row 0..127
        int c4 = idx & 31;
        int v = v0 + r;
        float4 val = make_float4(0.f, 0.f, 0.f, 0.f);
        if (v < V) val = *reinterpret_cast<const float4*>(nf + (size_t)v * NODE_IN + c4 * 4);
        *reinterpret_cast<float4*>(&xs[r * NODE_IN + c4 * 4]) = val;
    }
    __syncthreads();

    int cg = tid & 31;
    int w = tid >> 5;                     // warp 0..15 -> rows w*8..w*8+7

    unsigned long long an[8][2], arr[8][2];
    #pragma unroll
    for (int i = 0; i < 8; i++) {
        an[i][0] = an[i][1] = 0ull;
        arr[i][0] = arr[i][1] = 0ull;
    }

    for (int k4 = 0; k4 < NODE_IN / 4; k4++) {
        // hoist weights for these 4 k values (reused by all 8 rows)
        ulonglong2 wn[4], wr[4];
        #pragma unroll
        for (int kk = 0; kk < 4; kk++) {
            int k = k4 * 4 + kk;
            wn[kk] = *reinterpret_cast<const ulonglong2*>(Wn + (size_t)k * HF + cg * 4);
            wr[kk] = *reinterpret_cast<const ulonglong2*>(Wr + (size_t)k * HF + cg * 4);
        }
        #pragma unroll
        for (int i = 0; i < 8; i++) {
            float4 x4 = *reinterpret_cast<const float4*>(&xs[(w * 8 + i) * NODE_IN + k4 * 4]);
            unsigned long long xb;
            xb = pack2(x4.x);
            fma2(an[i][0], xb, wn[0].x); fma2(an[i][1], xb, wn[0].y);
            fma2(arr[i][0], xb, wr[0].x); fma2(arr[i][1], xb, wr[0].y);
            xb = pack2(x4.y);
            fma2(an[i][0], xb, wn[1].x); fma2(an[i][1], xb, wn[1].y);
            fma2(arr[i][0], xb, wr[1].x); fma2(arr[i][1], xb, wr[1].y);
            xb = pack2(x4.z);
            fma2(an[i][0], xb, wn[2].x); fma2(an[i][1], xb, wn[2].y);
            fma2(arr[i][0], xb, wr[2].x); fma2(arr[i][1], xb, wr[2].y);
            xb = pack2(x4.w);
            fma2(an[i][0], xb, wn[3].x); fma2(an[i][1], xb, wn[3].y);
            fma2(arr[i][0], xb, wr[3].x); fma2(arr[i][1], xb, wr[3].y);
        }
    }

    float4 b4 = *reinterpret_cast<const float4*>(bias + cg * 4);
    int h = cg >> 3;
    const float4 alv = __ldg(reinterpret_cast<const float4*>(al + h * OUTF + (cg & 7) * 4));
    const float4 arv = __ldg(reinterpret_cast<const float4*>(ar + h * OUTF + (cg & 7) * 4));

    #pragma unroll
    for (int i = 0; i < 8; i++) {
        int v = v0 + w * 8 + i;
        float2 n0 = unpack2(an[i][0]), n1 = unpack2(an[i][1]);
        float2 r0 = unpack2(arr[i][0]), r1 = unpack2(arr[i][1]);
        float4 fv = make_float4(n0.x, n0.y, n1.x, n1.y);
        float4 rv = make_float4(r0.x + b4.x, r0.y + b4.y, r1.x + b4.z, r1.y + b4.w);
        if (v < V) {
            *reinterpret_cast<float4*>(g_ft + (size_t)v * HF + cg * 4) = fv;
            *reinterpret_cast<float4*>(out + (size_t)v * HF + cg * 4) = rv;
        }
        float pl = fv.x * alv.x + fv.y * alv.y + fv.z * alv.z + fv.w * alv.w;
        float pr = fv.x * arv.x + fv.y * arv.y + fv.z * arv.z + fv.w * arv.w;
        pl += __shfl_xor_sync(0xFFFFFFFFu, pl, 1);
        pl += __shfl_xor_sync(0xFFFFFFFFu, pl, 2);
        pl += __shfl_xor_sync(0xFFFFFFFFu, pl, 4);
        pr += __shfl_xor_sync(0xFFFFFFFFu, pr, 1);
        pr += __shfl_xor_sync(0xFFFFFFFFu, pr, 2);
        pr += __shfl_xor_sync(0xFFFFFFFFu, pr, 4);
        if ((cg & 7) == 0 && v < V) {
            g_el[v * HEADS + h] = pl;
            g_er[v * HEADS + h] = pr;
        }
    }
}

// edge logits + exp + segment-sum denominator
__global__ void k_edge(const float* __restrict__ ef, const int* __restrict__ src,
                       const int* __restrict__ dst, int E)
{
    __shared__ float swer[EDGE_IN * HEADS];
    if (threadIdx.x < EDGE_IN * HEADS) swer[threadIdx.x] = g_wer[threadIdx.x];
    __syncthreads();

    int i = blockIdx.x * blockDim.x + threadIdx.x;
    if (i >= E) return;

    float efv[16];
    #pragma unroll
    for (int q = 0; q < 4; q++) {
        float4 e4 = __ldg(reinterpret_cast<const float4*>(ef + (size_t)i * EDGE_IN + q * 4));
        efv[q * 4 + 0] = e4.x; efv[q * 4 + 1] = e4.y; efv[q * 4 + 2] = e4.z; efv[q * 4 + 3] = e4.w;
    }
    float ee0 = 0.f, ee1 = 0.f, ee2 = 0.f, ee3 = 0.f;
    #pragma unroll
    for (int j = 0; j < EDGE_IN; j++) {
        float e = efv[j];
        ee0 += e * swer[j * 4 + 0];
        ee1 += e * swer[j * 4 + 1];
        ee2 += e * swer[j * 4 + 2];
        ee3 += e * swer[j * 4 + 3];
    }

    int s = src[i], d = dst[i];
    float4 el4 = *reinterpret_cast<const float4*>(&g_el[s * HEADS]);
    float4 er4 = *reinterpret_cast<const float4*>(&g_er[d * HEADS]);

    float t0 = el4.x + er4.x + ee0;
    float t1 = el4.y + er4.y + ee1;
    float t2 = el4.z + er4.z + ee2;
    float t3 = el4.w + er4.w + ee3;
    t0 = (t0 >= 0.f) ? t0 : NEG_SLOPE * t0;
    t1 = (t1 >= 0.f) ? t1 : NEG_SLOPE * t1;
    t2 = (t2 >= 0.f) ? t2 : NEG_SLOPE * t2;
    t3 = (t3 >= 0.f) ? t3 : NEG_SLOPE * t3;
    float x0 = __expf(t0), x1 = __expf(t1), x2 = __expf(t2), x3 = __expf(t3);

    *reinterpret_cast<float4*>(&g_ex[(size_t)i * HEADS]) = make_float4(x0, x1, x2, x3);

    float* ep = &g_esum[d * HEADS];
    asm volatile("red.global.add.v4.f32 [%0], {%1,%2,%3,%4};"
                 :: "l"(ep), "f"(x0), "f"(x1), "f"(x2), "f"(x3) : "memory");
}

// aggregation: one block per dst, warp-per-edge float4 gathers
__global__ void __launch_bounds__(128) k_agg(const int* __restrict__ src,
                                             float* __restrict__ out, int V)
{
    __shared__ int   s_src[ETILE];
    __shared__ float s_a[HEADS][ETILE];
    __shared__ float4 s_red[3][32];

    int v = blockIdx.x;
    int t = threadIdx.x, w = t >> 5, lane = t & 31;
    int beg = g_rowptr[v], end = g_rowptr[v + 1];
    if (end <= beg) return;

    float4 es = *reinterpret_cast<const float4*>(&g_esum[v * HEADS]);
    float iv0 = 1.0f / es.x, iv1 = 1.0f / es.y, iv2 = 1.0f / es.z, iv3 = 1.0f / es.w;

    int h = lane >> 3;
    float4 acc = make_float4(0.f, 0.f, 0.f, 0.f);

    for (int pos = beg; pos < end; pos += ETILE) {
        int cnt = min(ETILE, end - pos);
        __syncthreads();
        if (t < cnt) {
            int eid = g_csr[pos + t];
            s_src[t] = src[eid];
            float4 ex = *reinterpret_cast<const float4*>(&g_ex[(size_t)eid * HEADS]);
            s_a[0][t] = ex.x * iv0;
            s_a[1][t] = ex.y * iv1;
            s_a[2][t] = ex.z * iv2;
            s_a[3][t] = ex.w * iv3;
        }
        __syncthreads();
        #pragma unroll 2
        for (int j = w; j < cnt; j += 4) {
            int sv = s_src[j];
            float a = s_a[h][j];
            float4 f = __ldg(reinterpret_cast<const float4*>(g_ft + (size_t)sv * HF + lane * 4));
            acc.x += a * f.x; acc.y += a * f.y; acc.z += a * f.z; acc.w += a * f.w;
        }
    }

    if (w > 0) s_red[w - 1][lane] = acc;
    __syncthreads();
    if (w == 0) {
        acc.x += s_red[0][lane].x + s_red[1][lane].x + s_red[2][lane].x;
        acc.y += s_red[0][lane].y + s_red[1][lane].y + s_red[2][lane].y;
        acc.z += s_red[0][lane].z + s_red[1][lane].z + s_red[2][lane].z;
        acc.w += s_red[0][lane].w + s_red[1][lane].w + s_red[2][lane].w;
        float4* op = reinterpret_cast<float4*>(out + (size_t)v * HF + lane * 4);
        float4 o = *op;
        o.x += acc.x; o.y += acc.y; o.z += acc.z; o.w += acc.w;
        *op = o;
    }
}

// ---------------- launch with forked capture streams ----------------
static cudaStream_t g_s2 = nullptr;
static cudaEvent_t g_evFork = nullptr, g_evJoin = nullptr, g_evZ = nullptr;
static bool g_attr = false;

extern "C" void kernel_launch(void* const* d_in, const int* in_sizes, int n_in,
                              void* d_out, int out_size)
{
    const float* nf   = (const float*)d_in[0];
    const float* ef   = (const float*)d_in[1];
    const int*   src  = (const int*)d_in[2];
    const int*   dst  = (const int*)d_in[3];
    const float* Wn   = (const float*)d_in[4];
    const float* We   = (const float*)d_in[5];
    const float* al   = (const float*)d_in[6];
    const float* ar   = (const float*)d_in[7];
    const float* ae   = (const float*)d_in[8];
    const float* Wr   = (const float*)d_in[9];
    const float* bias = (const float*)d_in[10];
    float* out = (float*)d_out;

    int V = in_sizes[0] / NODE_IN;
    int E = in_sizes[2];
    if (V > MAXV) V = MAXV;
    if (E > MAXE) E = MAXE;

    if (!g_s2) {
        cudaStreamCreateWithFlags(&g_s2, cudaStreamNonBlocking);
        cudaEventCreateWithFlags(&g_evFork, cudaEventDisableTiming);
        cudaEventCreateWithFlags(&g_evJoin, cudaEventDisableTiming);
        cudaEventCreateWithFlags(&g_evZ, cudaEventDisableTiming);
    }
    const int smemProj = PROJ_ROWS * NODE_IN * sizeof(float);   // 64 KB
    if (!g_attr) {
        cudaFuncSetAttribute(k_nodeproj, cudaFuncAttributeMaxDynamicSharedMemorySize, smemProj);
        g_attr = true;
    }

    int nch = (V + 1023) / 1024;

    cudaEventRecord(g_evFork, 0);
    cudaStreamWaitEvent(g_s2, g_evFork, 0);

    k_fold<<<1, 64>>>(We, ae);                                     // #1 main
    k_zero<<<(V * HEADS + 255) / 256, 256, 0, g_s2>>>(V);          // #2 side
    cudaEventRecord(g_evZ, g_s2);
    k_hist<<<(E + 255) / 256, 256, 0, g_s2>>>(dst, E);             // #3 side
    k_nodeproj<<<(V + PROJ_ROWS - 1) / PROJ_ROWS, 512, smemProj>>>(nf, Wn, Wr, bias, al, ar, out, V);  // #4 main (profiled)
    k_scan1<<<nch, 1024, 0, g_s2>>>(V);                            // #5 side
    k_scan3<<<nch, 1024, 0, g_s2>>>(V);                            // #6 side
    k_fill<<<(E + 255) / 256, 256, 0, g_s2>>>(dst, E);             // #7 side
    cudaEventRecord(g_evJoin, g_s2);

    cudaStreamWaitEvent(0, g_evZ, 0);
    k_edge<<<(E + 127) / 128, 128>>>(ef, src, dst, E);             // #8 main

    cudaStreamWaitEvent(0, g_evJoin, 0);
    k_agg<<<V, 128>>>(src, out, V);                                // #9 main
}

// round 6
// speedup vs baseline: 1.9234x; 1.1766x over previous
#include <cuda_runtime.h>
#include <cstdint>

#define MAXV 50000
#define MAXE 800000
#define NODE_IN 128
#define EDGE_IN 16
#define HF 128
#define HEADS 4
#define OUTF 32
#define NEG_SLOPE 0.2f
#define ETILE 64
#define PROJ_ROWS 64
#define XS_LD 132   // padded smem stride (floats) -> conflict-free A frags

// ---------------- device scratch ----------------
__device__ float g_ft[MAXV * HF];
__device__ float g_el[MAXV * HEADS];
__device__ float g_er[MAXV * HEADS];
__device__ float g_esum[MAXV * HEADS];
__device__ float g_ex[MAXE * HEADS];
__device__ int   g_deg[MAXV];
__device__ int   g_incl[MAXV];
__device__ int   g_bsum[64];
__device__ int   g_rowptr[MAXV + 1];
__device__ int   g_cursor[MAXV];
__device__ int   g_csr[MAXE];
__device__ float g_wer[EDGE_IN * HEADS];
__device__ unsigned g_wnr[NODE_IN * HF];   // tf32-rounded Wn (bit patterns)
__device__ unsigned g_wrr[NODE_IN * HF];   // tf32-rounded Wr

__device__ __forceinline__ unsigned tf32r(float x) {
    unsigned u;
    asm("cvt.rna.tf32.f32 %0, %1;" : "=r"(u) : "f"(x));
    return u;
}

__device__ __forceinline__ void mma_tf32(float* d, const unsigned* a, const unsigned* b) {
    asm volatile(
        "mma.sync.aligned.m16n8k8.row.col.f32.tf32.tf32.f32 "
        "{%0,%1,%2,%3}, {%4,%5,%6,%7}, {%8,%9}, {%0,%1,%2,%3};"
        : "+f"(d[0]), "+f"(d[1]), "+f"(d[2]), "+f"(d[3])
        : "r"(a[0]), "r"(a[1]), "r"(a[2]), "r"(a[3]), "r"(b[0]), "r"(b[1]));
}

// ---------------- CSR-build kernels (side stream) ----------------
__global__ void k_zero(int V) {
    int i = blockIdx.x * blockDim.x + threadIdx.x;
    if (i < V) g_deg[i] = 0;
    if (i < V * HEADS) g_esum[i] = 0.0f;
}

__global__ void k_hist(const int* __restrict__ dst, int E) {
    int i = blockIdx.x * blockDim.x + threadIdx.x;
    if (i < E) atomicAdd(&g_deg[dst[i]], 1);
}

__global__ void k_scan1(int V) {
    __shared__ int wsum[32];
    int b = blockIdx.x, t = threadIdx.x;
    int i = b * 1024 + t;
    int val = (i < V) ? g_deg[i] : 0;
    int lane = t & 31, wid = t >> 5;
    int x = val;
    #pragma unroll
    for (int o = 1; o < 32; o <<= 1) {
        int y = __shfl_up_sync(0xFFFFFFFFu, x, o);
        if (lane >= o) x += y;
    }
    if (lane == 31) wsum[wid] = x;
    __syncthreads();
    if (wid == 0) {
        int s = wsum[lane];
        #pragma unroll
        for (int o = 1; o < 32; o <<= 1) {
            int y = __shfl_up_sync(0xFFFFFFFFu, s, o);
            if (lane >= o) s += y;
        }
        wsum[lane] = s;
    }
    __syncthreads();
    int incl = x + (wid > 0 ? wsum[wid - 1] : 0);
    if (i < V) g_incl[i] = incl;
    if (t == 1023) g_bsum[b] = incl;
}

__global__ void k_scan3(int V) {
    __shared__ int soff;
    int b = blockIdx.x, t = threadIdx.x;
    if (t < 32) {
        int s = 0;
        for (int j = t; j < b; j += 32) s += g_bsum[j];
        #pragma unroll
        for (int o = 16; o > 0; o >>= 1) s += __shfl_xor_sync(0xFFFFFFFFu, s, o);
        if (t == 0) soff = s;
    }
    __syncthreads();
    int i = b * 1024 + t;
    if (i < V) {
        int incl = g_incl[i] + soff;
        g_rowptr[i + 1] = incl;
        g_cursor[i] = incl - g_deg[i];
        if (i == 0) g_rowptr[0] = 0;
    }
}

__global__ void k_fill(const int* __restrict__ dst, int E) {
    int i = blockIdx.x * blockDim.x + threadIdx.x;
    if (i < E) {
        int pos = atomicAdd(&g_cursor[dst[i]], 1);
        g_csr[pos] = i;
    }
}

// ---------------- fold + tf32 weight rounding (one kernel) ----------------
__global__ void k_fold(const float* __restrict__ We, const float* __restrict__ ae,
                       const float* __restrict__ Wn, const float* __restrict__ Wr) {
    int i = blockIdx.x * blockDim.x + threadIdx.x;
    if (i < NODE_IN * HF) {
        g_wnr[i] = tf32r(Wn[i]);
        g_wrr[i] = tf32r(Wr[i]);
    }
    if (blockIdx.x == 0 && threadIdx.x < EDGE_IN * HEADS) {
        int t = threadIdx.x;
        int j = t >> 2, h = t & 3;
        float s = 0.0f;
        #pragma unroll
        for (int f = 0; f < OUTF; f++)
            s += We[j * HF + h * OUTF + f] * ae[h * OUTF + f];
        g_wer[j * HEADS + h] = s;
    }
}

// ---------------- node projection via TF32 HMMA ----------------
// 512 threads, 64-row tile. Warp grid 2 (rows) x 8 (col groups of 32).
// Warp tile: 2 m16 tiles x 4 n8 tiles over k=128 (16 k-steps).
// Col groups 0..3 -> ft (heads 0..3, fused el/er); 4..7 -> residual out + bias.
__global__ void __launch_bounds__(512) k_nodeproj(
    const float* __restrict__ nf, const float* __restrict__ bias,
    const float* __restrict__ al, const float* __restrict__ ar,
    float* __restrict__ out, int V)
{
    extern __shared__ float xs[];   // [64][XS_LD]
    int v0 = blockIdx.x * PROJ_ROWS;
    int tid = threadIdx.x;

    // stage + tf32-round node features
    #pragma unroll
    for (int i = 0; i < 4; i++) {
        int idx = tid + i * 512;          // 0..2047 float4 slots
        int r = idx >> 5;                 // row 0..63
        int c4 = idx & 31;
        int v = v0 + r;
        float4 val = make_float4(0.f, 0.f, 0.f, 0.f);
        if (v < V) val = *reinterpret_cast<const float4*>(nf + (size_t)v * NODE_IN + c4 * 4);
        val.x = __uint_as_float(tf32r(val.x));
        val.y = __uint_as_float(tf32r(val.y));
        val.z = __uint_as_float(tf32r(val.z));
        val.w = __uint_as_float(tf32r(val.w));
        *reinterpret_cast<float4*>(&xs[r * XS_LD + c4 * 4]) = val;
    }
    __syncthreads();

    int lane = tid & 31;
    int warp = tid >> 5;                  // 0..15
    int wrow = warp & 1;                  // row half: rows wrow*32 .. +31
    int wcg  = warp >> 1;                 // col group 0..7 (32 cols each)
    int tig  = lane & 3;
    int gid  = lane >> 2;

    const unsigned* B = (wcg < 4) ? g_wnr : g_wrr;
    int nb = (wcg & 3) * 32;
    int mbase = wrow * 32;

    float acc[2][4][4];
    #pragma unroll
    for (int mt = 0; mt < 2; mt++)
        #pragma unroll
        for (int nt = 0; nt < 4; nt++)
            #pragma unroll
            for (int q = 0; q < 4; q++) acc[mt][nt][q] = 0.f;

    #pragma unroll 4
    for (int ks = 0; ks < 16; ks++) {
        int kb = ks * 8;
        unsigned a[2][4];
        #pragma unroll
        for (int mt = 0; mt < 2; mt++) {
            int r0 = mbase + mt * 16 + gid;
            a[mt][0] = __float_as_uint(xs[r0 * XS_LD + kb + tig]);
            a[mt][1] = __float_as_uint(xs[(r0 + 8) * XS_LD + kb + tig]);
            a[mt][2] = __float_as_uint(xs[r0 * XS_LD + kb + tig + 4]);
            a[mt][3] = __float_as_uint(xs[(r0 + 8) * XS_LD + kb + tig + 4]);
        }
        unsigned b[4][2];
        #pragma unroll
        for (int nt = 0; nt < 4; nt++) {
            int col = nb + nt * 8 + gid;
            b[nt][0] = __ldg(&B[(kb + tig) * HF + col]);
            b[nt][1] = __ldg(&B[(kb + tig + 4) * HF + col]);
        }
        #pragma unroll
        for (int mt = 0; mt < 2; mt++)
            #pragma unroll
            for (int nt = 0; nt < 4; nt++)
                mma_tf32(acc[mt][nt], a[mt], b[nt]);
    }

    if (wcg < 4) {
        // ft store + fused el/er; head h = wcg
        int h = wcg;
        float2 alf[4], arf[4];
        #pragma unroll
        for (int nt = 0; nt < 4; nt++) {
            alf[nt] = *reinterpret_cast<const float2*>(al + h * OUTF + nt * 8 + 2 * tig);
            arf[nt] = *reinterpret_cast<const float2*>(ar + h * OUTF + nt * 8 + 2 * tig);
        }
        #pragma unroll
        for (int mt = 0; mt < 2; mt++) {
            int r0 = v0 + mbase + mt * 16 + gid;
            float el0 = 0.f, el1 = 0.f, er0 = 0.f, er1 = 0.f;
            #pragma unroll
            for (int nt = 0; nt < 4; nt++) {
                el0 += acc[mt][nt][0] * alf[nt].x + acc[mt][nt][1] * alf[nt].y;
                el1 += acc[mt][nt][2] * alf[nt].x + acc[mt][nt][3] * alf[nt].y;
                er0 += acc[mt][nt][0] * arf[nt].x + acc[mt][nt][1] * arf[nt].y;
                er1 += acc[mt][nt][2] * arf[nt].x + acc[mt][nt][3] * arf[nt].y;
                if (r0 < V)
                    *reinterpret_cast<float2*>(g_ft + (size_t)r0 * HF + h * OUTF + nt * 8 + 2 * tig)
                        = make_float2(acc[mt][nt][0], acc[mt][nt][1]);
                if (r0 + 8 < V)
                    *reinterpret_cast<float2*>(g_ft + (size_t)(r0 + 8) * HF + h * OUTF + nt * 8 + 2 * tig)
                        = make_float2(acc[mt][nt][2], acc[mt][nt][3]);
            }
            el0 += __shfl_xor_sync(0xFFFFFFFFu, el0, 1); el0 += __shfl_xor_sync(0xFFFFFFFFu, el0, 2);
            el1 += __shfl_xor_sync(0xFFFFFFFFu, el1, 1); el1 += __shfl_xor_sync(0xFFFFFFFFu, el1, 2);
            er0 += __shfl_xor_sync(0xFFFFFFFFu, er0, 1); er0 += __shfl_xor_sync(0xFFFFFFFFu, er0, 2);
            er1 += __shfl_xor_sync(0xFFFFFFFFu, er1, 1); er1 += __shfl_xor_sync(0xFFFFFFFFu, er1, 2);
            if (tig == 0) {
                if (r0 < V)     { g_el[r0 * HEADS + h] = el0;       g_er[r0 * HEADS + h] = er0; }
                if (r0 + 8 < V) { g_el[(r0 + 8) * HEADS + h] = el1; g_er[(r0 + 8) * HEADS + h] = er1; }
            }
        }
    } else {
        // residual + bias into out
        int cb = (wcg - 4) * 32;
        float2 bv[4];
        #pragma unroll
        for (int nt = 0; nt < 4; nt++)
            bv[nt] = *reinterpret_cast<const float2*>(bias + cb + nt * 8 + 2 * tig);
        #pragma unroll
        for (int mt = 0; mt < 2; mt++) {
            int r0 = v0 + mbase + mt * 16 + gid;
            #pragma unroll
            for (int nt = 0; nt < 4; nt++) {
                int col = cb + nt * 8 + 2 * tig;
                if (r0 < V)
                    *reinterpret_cast<float2*>(out + (size_t)r0 * HF + col)
                        = make_float2(acc[mt][nt][0] + bv[nt].x, acc[mt][nt][1] + bv[nt].y);
                if (r0 + 8 < V)
                    *reinterpret_cast<float2*>(out + (size_t)(r0 + 8) * HF + col)
                        = make_float2(acc[mt][nt][2] + bv[nt].x, acc[mt][nt][3] + bv[nt].y);
            }
        }
    }
}

// ---------------- edge logits + exp + segment-sum denominator -----------
__global__ void k_edge(const float* __restrict__ ef, const int* __restrict__ src,
                       const int* __restrict__ dst, int E)
{
    __shared__ float swer[EDGE_IN * HEADS];
    if (threadIdx.x < EDGE_IN * HEADS) swer[threadIdx.x] = g_wer[threadIdx.x];
    __syncthreads();

    int i = blockIdx.x * blockDim.x + threadIdx.x;
    if (i >= E) return;

    float efv[16];
    #pragma unroll
    for (int q = 0; q < 4; q++) {
        float4 e4 = __ldg(reinterpret_cast<const float4*>(ef + (size_t)i * EDGE_IN + q * 4));
        efv[q * 4 + 0] = e4.x; efv[q * 4 + 1] = e4.y; efv[q * 4 + 2] = e4.z; efv[q * 4 + 3] = e4.w;
    }
    float ee0 = 0.f, ee1 = 0.f, ee2 = 0.f, ee3 = 0.f;
    #pragma unroll
    for (int j = 0; j < EDGE_IN; j++) {
        float e = efv[j];
        ee0 += e * swer[j * 4 + 0];
        ee1 += e * swer[j * 4 + 1];
        ee2 += e * swer[j * 4 + 2];
        ee3 += e * swer[j * 4 + 3];
    }

    int s = src[i], d = dst[i];
    float4 el4 = *reinterpret_cast<const float4*>(&g_el[s * HEADS]);
    float4 er4 = *reinterpret_cast<const float4*>(&g_er[d * HEADS]);

    float t0 = el4.x + er4.x + ee0;
    float t1 = el4.y + er4.y + ee1;
    float t2 = el4.z + er4.z + ee2;
    float t3 = el4.w + er4.w + ee3;
    t0 = (t0 >= 0.f) ? t0 : NEG_SLOPE * t0;
    t1 = (t1 >= 0.f) ? t1 : NEG_SLOPE * t1;
    t2 = (t2 >= 0.f) ? t2 : NEG_SLOPE * t2;
    t3 = (t3 >= 0.f) ? t3 : NEG_SLOPE * t3;
    // softmax is shift-invariant; logits are O(1) -> no max pass
    float x0 = __expf(t0), x1 = __expf(t1), x2 = __expf(t2), x3 = __expf(t3);

    *reinterpret_cast<float4*>(&g_ex[(size_t)i * HEADS]) = make_float4(x0, x1, x2, x3);

    float* ep = &g_esum[d * HEADS];
    asm volatile("red.global.add.v4.f32 [%0], {%1,%2,%3,%4};"
                 :: "l"(ep), "f"(x0), "f"(x1), "f"(x2), "f"(x3) : "memory");
}

// ---------------- aggregation: one block per dst ----------------
__global__ void __launch_bounds__(128) k_agg(const int* __restrict__ src,
                                             float* __restrict__ out, int V)
{
    __shared__ int   s_src[ETILE];
    __shared__ float s_a[HEADS][ETILE];
    __shared__ float4 s_red[3][32];

    int v = blockIdx.x;
    int t = threadIdx.x, w = t >> 5, lane = t & 31;
    int beg = g_rowptr[v], end = g_rowptr[v + 1];
    if (end <= beg) return;

    float4 es = *reinterpret_cast<const float4*>(&g_esum[v * HEADS]);
    float iv0 = 1.0f / es.x, iv1 = 1.0f / es.y, iv2 = 1.0f / es.z, iv3 = 1.0f / es.w;

    int h = lane >> 3;
    float4 acc = make_float4(0.f, 0.f, 0.f, 0.f);

    for (int pos = beg; pos < end; pos += ETILE) {
        int cnt = min(ETILE, end - pos);
        __syncthreads();
        if (t < cnt) {
            int eid = g_csr[pos + t];
            s_src[t] = src[eid];
            float4 ex = *reinterpret_cast<const float4*>(&g_ex[(size_t)eid * HEADS]);
            s_a[0][t] = ex.x * iv0;
            s_a[1][t] = ex.y * iv1;
            s_a[2][t] = ex.z * iv2;
            s_a[3][t] = ex.w * iv3;
        }
        __syncthreads();
        #pragma unroll 2
        for (int j = w; j < cnt; j += 4) {
            int sv = s_src[j];
            float a = s_a[h][j];
            float4 f = __ldg(reinterpret_cast<const float4*>(g_ft + (size_t)sv * HF + lane * 4));
            acc.x += a * f.x; acc.y += a * f.y; acc.z += a * f.z; acc.w += a * f.w;
        }
    }

    if (w > 0) s_red[w - 1][lane] = acc;
    __syncthreads();
    if (w == 0) {
        acc.x += s_red[0][lane].x + s_red[1][lane].x + s_red[2][lane].x;
        acc.y += s_red[0][lane].y + s_red[1][lane].y + s_red[2][lane].y;
        acc.z += s_red[0][lane].z + s_red[1][lane].z + s_red[2][lane].z;
        acc.w += s_red[0][lane].w + s_red[1][lane].w + s_red[2][lane].w;
        float4* op = reinterpret_cast<float4*>(out + (size_t)v * HF + lane * 4);
        float4 o = *op;
        o.x += acc.x; o.y += acc.y; o.z += acc.z; o.w += acc.w;
        *op = o;
    }
}

// ---------------- launch with forked capture streams ----------------
static cudaStream_t g_s2 = nullptr;
static cudaEvent_t g_evFork = nullptr, g_evJoin = nullptr, g_evZ = nullptr;

extern "C" void kernel_launch(void* const* d_in, const int* in_sizes, int n_in,
                              void* d_out, int out_size)
{
    const float* nf   = (const float*)d_in[0];
    const float* ef   = (const float*)d_in[1];
    const int*   src  = (const int*)d_in[2];
    const int*   dst  = (const int*)d_in[3];
    const float* Wn   = (const float*)d_in[4];
    const float* We   = (const float*)d_in[5];
    const float* al   = (const float*)d_in[6];
    const float* ar   = (const float*)d_in[7];
    const float* ae   = (const float*)d_in[8];
    const float* Wr   = (const float*)d_in[9];
    const float* bias = (const float*)d_in[10];
    float* out = (float*)d_out;

    int V = in_sizes[0] / NODE_IN;
    int E = in_sizes[2];
    if (V > MAXV) V = MAXV;
    if (E > MAXE) E = MAXE;

    if (!g_s2) {
        cudaStreamCreateWithFlags(&g_s2, cudaStreamNonBlocking);
        cudaEventCreateWithFlags(&g_evFork, cudaEventDisableTiming);
        cudaEventCreateWithFlags(&g_evJoin, cudaEventDisableTiming);
        cudaEventCreateWithFlags(&g_evZ, cudaEventDisableTiming);
    }

    const int smemProj = PROJ_ROWS * XS_LD * sizeof(float);   // ~33.8 KB
    int nch = (V + 1023) / 1024;

    cudaEventRecord(g_evFork, 0);
    cudaStreamWaitEvent(g_s2, g_evFork, 0);

    k_fold<<<(NODE_IN * HF + 255) / 256, 256>>>(We, ae, Wn, Wr);   // #1 main (fold + tf32 round)
    k_zero<<<(V * HEADS + 255) / 256, 256, 0, g_s2>>>(V);          // #2 side
    cudaEventRecord(g_evZ, g_s2);
    k_hist<<<(E + 255) / 256, 256, 0, g_s2>>>(dst, E);             // #3 side
    k_nodeproj<<<(V + PROJ_ROWS - 1) / PROJ_ROWS, 512, smemProj>>>(nf, bias, al, ar, out, V);  // #4 main (profiled)
    k_scan1<<<nch, 1024, 0, g_s2>>>(V);                            // #5 side
    k_scan3<<<nch, 1024, 0, g_s2>>>(V);                            // #6 side
    k_fill<<<(E + 255) / 256, 256, 0, g_s2>>>(dst, E);             // #7 side
    cudaEventRecord(g_evJoin, g_s2);

    cudaStreamWaitEvent(0, g_evZ, 0);
    k_edge<<<(E + 127) / 128, 128>>>(ef, src, dst, E);             // #8 main

    cudaStreamWaitEvent(0, g_evJoin, 0);
    k_agg<<<V, 128>>>(src, out, V);                                // #9 main
}